// round 2
// baseline (speedup 1.0000x reference)
#include <cuda_runtime.h>
#include <math.h>

// ---------------- scratch (no allocations allowed) ----------------
__device__ __align__(16) float g_bufA[100 * 6400];   // conv ping (max: c5 out 64*10*10)
__device__ __align__(16) float g_bufB[100 * 4608];   // conv pong (max: c4 out 32*12*12)
__device__ __align__(16) float g_q[4 * 100 * 128];
__device__ __align__(16) float g_k[4 * 100 * 128];
__device__ __align__(16) float g_v[4 * 100 * 256];
__device__ __align__(16) float g_o[100 * 1024];      // attention out, pre-concatenated
__device__ __align__(16) float g_t[100 * 2048];      // FFN hidden

// ---------------- conv1: reads patches straight from x ----------------
__global__ void conv1_kernel(const float* __restrict__ x, const float* __restrict__ w,
                             const float* __restrict__ b, float* __restrict__ out) {
    __shared__ float s_in[3 * 20 * 20];
    __shared__ float s_w[8 * 3 * 9];
    __shared__ float s_b[8];
    const int p = blockIdx.x;
    const int r0 = 20 * (p % 10);   // row block = j
    const int c0 = 20 * (p / 10);   // col block = i
    for (int idx = threadIdx.x; idx < 1200; idx += blockDim.x) {
        int c = idx / 400, rem = idx % 400, y = rem / 20, xx = rem % 20;
        s_in[idx] = x[c * 40000 + (r0 + y) * 200 + c0 + xx];
    }
    for (int idx = threadIdx.x; idx < 216; idx += blockDim.x) s_w[idx] = w[idx];
    if (threadIdx.x < 8) s_b[threadIdx.x] = b[threadIdx.x];
    __syncthreads();
    for (int idx = threadIdx.x; idx < 8 * 18 * 18; idx += blockDim.x) {
        int oc = idx / 324, rem = idx % 324, oy = rem / 18, ox = rem % 18;
        float acc = s_b[oc];
        const float* wp = s_w + oc * 27;
#pragma unroll
        for (int ci = 0; ci < 3; ci++)
#pragma unroll
            for (int ky = 0; ky < 3; ky++)
#pragma unroll
                for (int kx = 0; kx < 3; kx++)
                    acc += s_in[ci * 400 + (oy + ky) * 20 + ox + kx] * wp[ci * 9 + ky * 3 + kx];
        out[p * 2592 + idx] = acc;  // no relu on conv1
    }
}

// ---------------- generic conv: weights staged in smem, thread-per-output ----------------
template <int CI, int CO, int SIN, int KS, bool RELU>
__global__ void conv_smemw(const float* __restrict__ in, const float* __restrict__ w,
                           const float* __restrict__ bias, float* __restrict__ out) {
    constexpr int SOUT = SIN - KS + 1;
    extern __shared__ float sm[];
    float* s_in = sm;
    float* s_w = sm + CI * SIN * SIN;
    float* s_b = s_w + CO * CI * KS * KS;
    const int p = blockIdx.x;
    const float* inp = in + (size_t)p * CI * SIN * SIN;
    for (int idx = threadIdx.x; idx < CI * SIN * SIN; idx += blockDim.x) s_in[idx] = inp[idx];
    for (int idx = threadIdx.x; idx < CO * CI * KS * KS; idx += blockDim.x) s_w[idx] = w[idx];
    for (int idx = threadIdx.x; idx < CO; idx += blockDim.x) s_b[idx] = bias[idx];
    __syncthreads();
    for (int idx = threadIdx.x; idx < CO * SOUT * SOUT; idx += blockDim.x) {
        int oc = idx / (SOUT * SOUT), rem = idx % (SOUT * SOUT);
        int oy = rem / SOUT, ox = rem % SOUT;
        float acc = s_b[oc];
        const float* wp = s_w + oc * CI * KS * KS;
#pragma unroll 4
        for (int ci = 0; ci < CI; ci++)
#pragma unroll
            for (int ky = 0; ky < KS; ky++)
#pragma unroll
                for (int kx = 0; kx < KS; kx++)
                    acc += s_in[ci * SIN * SIN + (oy + ky) * SIN + ox + kx] *
                           wp[ci * KS * KS + ky * KS + kx];
        if (RELU) acc = fmaxf(acc, 0.f);
        out[(size_t)p * CO * SOUT * SOUT + idx] = acc;
    }
}

// ---------------- conv, register accumulators per-oc (weights too big for smem) ----------------
template <int CI, int CO, int SIN, int KS, bool RELU, int CHUNK>
__global__ void conv_reg(const float* __restrict__ in, const float* __restrict__ w,
                         const float* __restrict__ bias, float* __restrict__ out) {
    constexpr int SOUT = SIN - KS + 1;
    constexpr int SP = SOUT * SOUT;
    __shared__ float s_in[CI * SIN * SIN];
    const int p = blockIdx.x;
    const float* inp = in + (size_t)p * CI * SIN * SIN;
    for (int idx = threadIdx.x; idx < CI * SIN * SIN; idx += blockDim.x) s_in[idx] = inp[idx];
    __syncthreads();
    const int oc = threadIdx.x % CO;
    const int s = threadIdx.x / CO;
    int off[CHUNK];
#pragma unroll
    for (int u = 0; u < CHUNK; u++) {
        int pos = s * CHUNK + u;
        off[u] = (pos / SOUT) * SIN + (pos % SOUT);
    }
    float acc[CHUNK];
#pragma unroll
    for (int u = 0; u < CHUNK; u++) acc[u] = 0.f;
    const float* wp = w + (size_t)oc * CI * KS * KS;
    for (int ci = 0; ci < CI; ci++) {
        const float* ib = s_in + ci * SIN * SIN;
#pragma unroll
        for (int ky = 0; ky < KS; ky++)
#pragma unroll
            for (int kx = 0; kx < KS; kx++) {
                float wv = *wp++;
                const float* ip = ib + ky * SIN + kx;
#pragma unroll
                for (int u = 0; u < CHUNK; u++) acc[u] += wv * ip[off[u]];
            }
    }
    float bv = bias[oc];
#pragma unroll
    for (int u = 0; u < CHUNK; u++) {
        float r = acc[u] + bv;
        if (RELU) r = fmaxf(r, 0.f);
        out[(size_t)p * CO * SP + oc * SP + s * CHUNK + u] = r;
    }
}

// ---------------- conv10 (2x2, 256->512) fused with location embedding, writes h ----------------
__global__ void conv10_kernel(const float* __restrict__ in, const float* __restrict__ w,
                              const float* __restrict__ b, float* __restrict__ h) {
    __shared__ float s_in[1024];
    const int p = blockIdx.x;
    const int oc = threadIdx.x;  // 512 threads
    for (int idx = threadIdx.x; idx < 1024; idx += blockDim.x) s_in[idx] = in[p * 1024 + idx];
    __syncthreads();
    float acc = b[oc];
    const float* wp = w + oc * 1024;
#pragma unroll 8
    for (int i = 0; i < 1024; i++) acc += wp[i] * s_in[i];
    // location embedding: pos = 20*(p/10); emb[k<256]=sin(pos/10000^(2k/256)), else cos
    float pos = 20.f * (float)(p / 10);
    int kk = (oc < 256) ? oc : oc - 256;
    float inv = exp2f(-(2.f * (float)kk / 256.f) * 13.287712379549449f);  // log2(10000)
    float ang = pos * inv;
    acc += (oc < 256) ? sinf(ang) : cosf(ang);
    h[p * 512 + oc] = acc;
}

// ---------------- generic tiled fp32 GEMM: C[z] = A @ B[z] (+bias)(+relu)(+=C) ----------------
// 64x64 tile, BK=16, 256 threads, 4x4 per thread. N, K multiples of 64/16; M guarded.
template <bool RELU, bool HASBIAS, bool RESID>
__global__ __launch_bounds__(256) void gemm64(
    const float* __restrict__ A, const float* __restrict__ B,
    const float* __restrict__ bias, float* __restrict__ C,
    int M, int N, int K, int lda, int ldb, int ldc,
    long long sB, long long sC) {
    B += (long long)blockIdx.z * sB;
    C += (long long)blockIdx.z * sC;
    __shared__ __align__(16) float As[16][64];
    __shared__ __align__(16) float Bs[16][64];
    const int tid = threadIdx.x;
    const int m0 = blockIdx.y * 64, n0 = blockIdx.x * 64;
    const int ty = tid >> 4, tx = tid & 15;
    const int am = tid >> 2, ak4 = (tid & 3) << 2;
    const int bk = tid >> 4, bn4 = (tid & 15) << 2;
    float acc[4][4] = {};
    for (int k0 = 0; k0 < K; k0 += 16) {
        float4 av = make_float4(0.f, 0.f, 0.f, 0.f);
        if (m0 + am < M) av = *(const float4*)(A + (long long)(m0 + am) * lda + k0 + ak4);
        As[ak4 + 0][am] = av.x;
        As[ak4 + 1][am] = av.y;
        As[ak4 + 2][am] = av.z;
        As[ak4 + 3][am] = av.w;
        *(float4*)(&Bs[bk][bn4]) = *(const float4*)(B + (long long)(k0 + bk) * ldb + n0 + bn4);
        __syncthreads();
#pragma unroll
        for (int kk = 0; kk < 16; kk++) {
            float4 a4 = *(const float4*)(&As[kk][ty << 2]);
            float4 b4 = *(const float4*)(&Bs[kk][tx << 2]);
            acc[0][0] += a4.x * b4.x; acc[0][1] += a4.x * b4.y; acc[0][2] += a4.x * b4.z; acc[0][3] += a4.x * b4.w;
            acc[1][0] += a4.y * b4.x; acc[1][1] += a4.y * b4.y; acc[1][2] += a4.y * b4.z; acc[1][3] += a4.y * b4.w;
            acc[2][0] += a4.z * b4.x; acc[2][1] += a4.z * b4.y; acc[2][2] += a4.z * b4.z; acc[2][3] += a4.z * b4.w;
            acc[3][0] += a4.w * b4.x; acc[3][1] += a4.w * b4.y; acc[3][2] += a4.w * b4.z; acc[3][3] += a4.w * b4.w;
        }
        __syncthreads();
    }
#pragma unroll
    for (int i = 0; i < 4; i++) {
        int m = m0 + (ty << 2) + i;
        if (m >= M) break;
#pragma unroll
        for (int j = 0; j < 4; j++) {
            int n = n0 + (tx << 2) + j;
            float v = acc[i][j];
            if (HASBIAS) v += bias[n];
            if (RELU) v = fmaxf(v, 0.f);
            if (RESID) v += C[(long long)m * ldc + n];
            C[(long long)m * ldc + n] = v;
        }
    }
}

// ---------------- fused attention: per (query n, head h) block ----------------
// S = QK^T * 0.1, softmax over keys, O = A @ V, written pre-concatenated [100, 1024]
__global__ void attn_kernel(const float* __restrict__ Q, const float* __restrict__ K,
                            const float* __restrict__ V, float* __restrict__ O) {
    const int n = blockIdx.x, h = blockIdx.y;
    __shared__ float sq[128];
    __shared__ float sa[100];
    __shared__ float red[8];
    const int tid = threadIdx.x;
    if (tid < 128) sq[tid] = Q[(h * 100 + n) * 128 + tid];
    __syncthreads();
    float s = -1e30f;
    if (tid < 100) {
        const float* kr = K + (h * 100 + tid) * 128;
        float acc = 0.f;
#pragma unroll 8
        for (int i = 0; i < 128; i++) acc += sq[i] * kr[i];
        s = acc * 0.1f;  // 1/sqrt(100)
    }
    // block max
    float v = s;
#pragma unroll
    for (int o = 16; o; o >>= 1) v = fmaxf(v, __shfl_xor_sync(0xffffffffu, v, o));
    if ((tid & 31) == 0) red[tid >> 5] = v;
    __syncthreads();
    float mx = red[0];
#pragma unroll
    for (int i = 1; i < 8; i++) mx = fmaxf(mx, red[i]);
    float e = (tid < 100) ? expf(s - mx) : 0.f;
    float sv = e;
#pragma unroll
    for (int o = 16; o; o >>= 1) sv += __shfl_xor_sync(0xffffffffu, sv, o);
    __syncthreads();  // everyone done reading red (max) before overwrite
    if ((tid & 31) == 0) red[tid >> 5] = sv;
    __syncthreads();
    float sum = 0.f;
#pragma unroll
    for (int i = 0; i < 8; i++) sum += red[i];
    if (tid < 100) sa[tid] = e / sum;
    __syncthreads();
    // O[n, h*256 + v]
    const float* vb = V + h * 100 * 256;
    float acc = 0.f;
#pragma unroll 4
    for (int m = 0; m < 100; m++) acc += sa[m] * vb[m * 256 + tid];
    O[n * 1024 + h * 256 + tid] = acc;
}

// ---------------- host launcher ----------------
extern "C" void kernel_launch(void* const* d_in, const int* in_sizes, int n_in,
                              void* d_out, int out_size) {
    const float* x = (const float*)d_in[0];
    const float* cw[10];
    const float* cb[10];
    for (int i = 0; i < 10; i++) {
        cw[i] = (const float*)d_in[1 + 2 * i];
        cb[i] = (const float*)d_in[2 + 2 * i];
    }
    const float* Wq = (const float*)d_in[21];
    const float* Wk = (const float*)d_in[22];
    const float* Wv = (const float*)d_in[23];
    const float* Wo = (const float*)d_in[24];
    const float* W1 = (const float*)d_in[25];
    const float* b1 = (const float*)d_in[26];
    const float* W2 = (const float*)d_in[27];
    const float* b2 = (const float*)d_in[28];
    float* h = (float*)d_out;  // h lives in the output buffer

    float *bufA, *bufB, *q, *k, *v, *o, *t;
    cudaGetSymbolAddress((void**)&bufA, g_bufA);
    cudaGetSymbolAddress((void**)&bufB, g_bufB);
    cudaGetSymbolAddress((void**)&q, g_q);
    cudaGetSymbolAddress((void**)&k, g_k);
    cudaGetSymbolAddress((void**)&v, g_v);
    cudaGetSymbolAddress((void**)&o, g_o);
    cudaGetSymbolAddress((void**)&t, g_t);

    // dynamic smem opt-in for big conv layers
    constexpr int SM2 = (8 * 18 * 18 + 16 * 8 * 9 + 16) * 4;
    constexpr int SM3 = (16 * 16 * 16 + 32 * 16 * 9 + 32) * 4;
    constexpr int SM4 = (32 * 14 * 14 + 32 * 32 * 9 + 32) * 4;
    constexpr int SM5 = (32 * 12 * 12 + 64 * 32 * 9 + 64) * 4;
    constexpr int SM6 = (64 * 10 * 10 + 64 * 64 * 9 + 64) * 4;
    cudaFuncSetAttribute(conv_smemw<32, 32, 14, 3, true>,
                         cudaFuncAttributeMaxDynamicSharedMemorySize, SM4);
    cudaFuncSetAttribute(conv_smemw<32, 64, 12, 3, true>,
                         cudaFuncAttributeMaxDynamicSharedMemorySize, SM5);
    cudaFuncSetAttribute(conv_smemw<64, 64, 10, 3, true>,
                         cudaFuncAttributeMaxDynamicSharedMemorySize, SM6);

    // ---- conv stack (100 blocks = 100 patches) ----
    conv1_kernel<<<100, 256>>>(x, cw[0], cb[0], bufA);                               // 3->8, 18x18
    conv_smemw<8, 16, 18, 3, true><<<100, 256, SM2>>>(bufA, cw[1], cb[1], bufB);     // 16x16
    conv_smemw<16, 32, 16, 3, false><<<100, 256, SM3>>>(bufB, cw[2], cb[2], bufA);   // 14x14
    conv_smemw<32, 32, 14, 3, true><<<100, 256, SM4>>>(bufA, cw[3], cb[3], bufB);    // 12x12
    conv_smemw<32, 64, 12, 3, true><<<100, 256, SM5>>>(bufB, cw[4], cb[4], bufA);    // 10x10
    conv_smemw<64, 64, 10, 3, true><<<100, 256, SM6>>>(bufA, cw[5], cb[5], bufB);    // 8x8
    conv_reg<64, 128, 8, 3, true, 18><<<100, 256>>>(bufB, cw[6], cb[6], bufA);       // 6x6
    conv_reg<128, 128, 6, 3, true, 8><<<100, 256>>>(bufA, cw[7], cb[7], bufB);       // 4x4
    conv_reg<128, 256, 4, 3, true, 4><<<100, 256>>>(bufB, cw[8], cb[8], bufA);       // 2x2
    conv10_kernel<<<100, 512>>>(bufA, cw[9], cb[9], h);  // 1x1, + location embedding

    // ---- 12 encoder layers ----
    for (int l = 0; l < 12; l++) {
        const float* wq = Wq + (size_t)l * 4 * 512 * 128;
        const float* wk = Wk + (size_t)l * 4 * 512 * 128;
        const float* wv = Wv + (size_t)l * 4 * 512 * 256;
        const float* wo = Wo + (size_t)l * 1024 * 512;
        const float* w1 = W1 + (size_t)l * 512 * 2048;
        const float* bb1 = b1 + (size_t)l * 2048;
        const float* w2 = W2 + (size_t)l * 2048 * 512;
        const float* bb2 = b2 + (size_t)l * 512;

        // Q, K, V (batched over 4 heads via grid.z)
        gemm64<false, false, false><<<dim3(2, 2, 4), 256>>>(
            h, wq, nullptr, q, 100, 128, 512, 512, 128, 128, 512LL * 128, 100LL * 128);
        gemm64<false, false, false><<<dim3(2, 2, 4), 256>>>(
            h, wk, nullptr, k, 100, 128, 512, 512, 128, 128, 512LL * 128, 100LL * 128);
        gemm64<false, false, false><<<dim3(4, 2, 4), 256>>>(
            h, wv, nullptr, v, 100, 256, 512, 512, 256, 256, 512LL * 256, 100LL * 256);
        // fused scores+softmax+AV, writes concat layout
        attn_kernel<<<dim3(100, 4), 256>>>(q, k, v, o);
        // h += O @ Wo
        gemm64<false, false, true><<<dim3(8, 2, 1), 256>>>(
            o, wo, nullptr, h, 100, 512, 1024, 1024, 512, 512, 0, 0);
        // t = relu(h @ W1 + b1)
        gemm64<true, true, false><<<dim3(32, 2, 1), 256>>>(
            h, w1, bb1, t, 100, 2048, 512, 512, 2048, 2048, 0, 0);
        // h += t @ W2 + b2
        gemm64<false, true, true><<<dim3(8, 2, 1), 256>>>(
            t, w2, bb2, h, 100, 512, 2048, 2048, 512, 512, 0, 0);
    }
}

// round 5
// speedup vs baseline: 2.3529x; 2.3529x over previous
#include <cuda_runtime.h>
#include <math.h>

// ---------------- scratch (no allocations allowed) ----------------
__device__ __align__(16) float g_bufA[100 * 6400];
__device__ __align__(16) float g_bufB[100 * 4608];
__device__ __align__(16) float g_z[100 * 2048];      // packed QKV: [n][q512|k512|v1024]
__device__ __align__(16) float g_o[100 * 1024];      // attention out, concat heads
__device__ __align__(16) float g_t[100 * 2048];      // FFN hidden
__device__ __align__(16) float g_part[4 * 100 * 512];// split-K partials

// ---------------- conv1: reads patches straight from x ----------------
__global__ void conv1_kernel(const float* __restrict__ x, const float* __restrict__ w,
                             const float* __restrict__ b, float* __restrict__ out) {
    __shared__ float s_in[3 * 20 * 20];
    __shared__ float s_w[8 * 3 * 9];
    __shared__ float s_b[8];
    const int p = blockIdx.x;
    const int r0 = 20 * (p % 10);
    const int c0 = 20 * (p / 10);
    for (int idx = threadIdx.x; idx < 1200; idx += blockDim.x) {
        int c = idx / 400, rem = idx % 400, y = rem / 20, xx = rem % 20;
        s_in[idx] = x[c * 40000 + (r0 + y) * 200 + c0 + xx];
    }
    for (int idx = threadIdx.x; idx < 216; idx += blockDim.x) s_w[idx] = w[idx];
    if (threadIdx.x < 8) s_b[threadIdx.x] = b[threadIdx.x];
    __syncthreads();
    for (int idx = threadIdx.x; idx < 8 * 18 * 18; idx += blockDim.x) {
        int oc = idx / 324, rem = idx % 324, oy = rem / 18, ox = rem % 18;
        float acc = s_b[oc];
        const float* wp = s_w + oc * 27;
#pragma unroll
        for (int ci = 0; ci < 3; ci++)
#pragma unroll
            for (int ky = 0; ky < 3; ky++)
#pragma unroll
                for (int kx = 0; kx < 3; kx++)
                    acc += s_in[ci * 400 + (oy + ky) * 20 + ox + kx] * wp[ci * 9 + ky * 3 + kx];
        out[p * 2592 + idx] = acc;
    }
}

// ---------------- register-tiled conv: OCT oc x CHUNK spatial per thread ----------------
// Per-ci weight slice staged in smem; FMA:smem-load ratio = OCT*CHUNK/(OCT+CHUNK).
template <int CI, int CO, int SIN, int OCT, int CHUNK, bool RELU, int NT>
__global__ __launch_bounds__(NT) void conv_tile(const float* __restrict__ in,
                                                const float* __restrict__ w,
                                                const float* __restrict__ bias,
                                                float* __restrict__ out) {
    constexpr int KK = 9;
    constexpr int SOUT = SIN - 2;
    constexpr int SP = SOUT * SOUT;
    constexpr int SS = SIN * SIN;
    constexpr int NOC = CO / OCT;
    constexpr int NSP = SP / CHUNK;
    static_assert(NOC * NSP == NT, "thread count mismatch");
    __shared__ float s_in[CI * SS];
    __shared__ float s_w[CO * KK];
    const int p = blockIdx.x;
    const float* inp = in + (size_t)p * CI * SS;
    for (int i = threadIdx.x; i < CI * SS; i += NT) s_in[i] = inp[i];
    const int ocg = threadIdx.x / NSP;
    const int spg = threadIdx.x % NSP;
    const int oc0 = ocg * OCT, sp0 = spg * CHUNK;
    int off[CHUNK];
#pragma unroll
    for (int u = 0; u < CHUNK; u++) {
        int pos = sp0 + u;
        off[u] = (pos / SOUT) * SIN + (pos % SOUT);
    }
    float acc[OCT][CHUNK];
#pragma unroll
    for (int o = 0; o < OCT; o++)
#pragma unroll
        for (int u = 0; u < CHUNK; u++) acc[o][u] = 0.f;
    for (int ci = 0; ci < CI; ci++) {
        __syncthreads();
        for (int i = threadIdx.x; i < CO * KK; i += NT)
            s_w[i] = w[(i / KK) * (CI * KK) + ci * KK + (i % KK)];
        __syncthreads();
        const float* ib = s_in + ci * SS;
#pragma unroll
        for (int ky = 0; ky < 3; ky++)
#pragma unroll
            for (int kx = 0; kx < 3; kx++) {
                float wf[OCT];
#pragma unroll
                for (int o = 0; o < OCT; o++) wf[o] = s_w[(oc0 + o) * KK + ky * 3 + kx];
                float xf[CHUNK];
                const float* ip = ib + ky * SIN + kx;
#pragma unroll
                for (int u = 0; u < CHUNK; u++) xf[u] = ip[off[u]];
#pragma unroll
                for (int o = 0; o < OCT; o++)
#pragma unroll
                    for (int u = 0; u < CHUNK; u++) acc[o][u] += wf[o] * xf[u];
            }
    }
#pragma unroll
    for (int o = 0; o < OCT; o++) {
        float bv = bias[oc0 + o];
#pragma unroll
        for (int u = 0; u < CHUNK; u++) {
            float r = acc[o][u] + bv;
            if (RELU) r = fmaxf(r, 0.f);
            out[(size_t)p * CO * SP + (oc0 + o) * SP + sp0 + u] = r;
        }
    }
}

// ---------------- skinny GEMM core: 64x32 tile, 128 threads, 4x4/thread ----------------
#define GEMM_CORE(A_, lda_, BLOAD, KSTART, KLEN)                                        \
    __shared__ __align__(16) float As[16][64];                                          \
    __shared__ __align__(16) float Bs[16][32];                                          \
    const int t = threadIdx.x;                                                          \
    const int ty = t >> 3, tx = t & 7;                                                  \
    const int am = t >> 2, ak4 = (t & 3) << 2;                                          \
    const int bk = t >> 3, bn4 = (t & 7) << 2;                                          \
    float acc[4][4] = {};                                                               \
    for (int kk0 = (KSTART); kk0 < (KSTART) + (KLEN); kk0 += 16) {                      \
        float4 a0 = make_float4(0.f, 0.f, 0.f, 0.f), a1 = a0;                           \
        if (m0 + am < M) a0 = *(const float4*)((A_) + (long long)(m0 + am) * (lda_) + kk0 + ak4); \
        if (m0 + am + 32 < M)                                                           \
            a1 = *(const float4*)((A_) + (long long)(m0 + am + 32) * (lda_) + kk0 + ak4);\
        As[ak4 + 0][am] = a0.x; As[ak4 + 1][am] = a0.y;                                 \
        As[ak4 + 2][am] = a0.z; As[ak4 + 3][am] = a0.w;                                 \
        As[ak4 + 0][am + 32] = a1.x; As[ak4 + 1][am + 32] = a1.y;                       \
        As[ak4 + 2][am + 32] = a1.z; As[ak4 + 3][am + 32] = a1.w;                       \
        BLOAD;                                                                          \
        __syncthreads();                                                                \
        _Pragma("unroll")                                                               \
        for (int kk = 0; kk < 16; kk++) {                                               \
            float4 a4 = *(const float4*)(&As[kk][ty << 2]);                             \
            float4 b4 = *(const float4*)(&Bs[kk][tx << 2]);                             \
            acc[0][0] += a4.x * b4.x; acc[0][1] += a4.x * b4.y;                         \
            acc[0][2] += a4.x * b4.z; acc[0][3] += a4.x * b4.w;                         \
            acc[1][0] += a4.y * b4.x; acc[1][1] += a4.y * b4.y;                         \
            acc[1][2] += a4.y * b4.z; acc[1][3] += a4.y * b4.w;                         \
            acc[2][0] += a4.z * b4.x; acc[2][1] += a4.z * b4.y;                         \
            acc[2][2] += a4.z * b4.z; acc[2][3] += a4.z * b4.w;                         \
            acc[3][0] += a4.w * b4.x; acc[3][1] += a4.w * b4.y;                         \
            acc[3][2] += a4.w * b4.z; acc[3][3] += a4.w * b4.w;                         \
        }                                                                               \
        __syncthreads();                                                                \
    }

// generic: C = A@B with optional bias/relu/resid, or plain store (split-K partial)
template <bool RELU, bool BIAS, bool RESID, bool PLAIN>
__global__ __launch_bounds__(128) void gemmS(const float* __restrict__ A,
                                             const float* __restrict__ B,
                                             const float* __restrict__ bias,
                                             float* __restrict__ C, int M, int N, int K,
                                             int lda, int ldb, int ldc, int kPerZ,
                                             long long strideCz) {
    const int m0 = blockIdx.y * 64, n0 = blockIdx.x * 32;
    const int z = blockIdx.z;
    C += (long long)z * strideCz;
    GEMM_CORE(A, lda,
              { *(float4*)(&Bs[bk][bn4]) =
                    *(const float4*)(B + (long long)(kk0 + bk) * ldb + n0 + bn4); },
              z * kPerZ, kPerZ)
#pragma unroll
    for (int i = 0; i < 4; i++) {
        int m = m0 + (ty << 2) + i;
        if (m >= M) break;
#pragma unroll
        for (int j = 0; j < 4; j++) {
            int n = n0 + (tx << 2) + j;
            float v = acc[i][j];
            if (!PLAIN) {
                if (BIAS) v += bias[n];
                if (RELU) v = fmaxf(v, 0.f);
                if (RESID) v += C[(long long)m * ldc + n];
            }
            C[(long long)m * ldc + n] = v;
        }
    }
}

// fused QKV: Z[100,2048] = h @ [Wq|Wk|Wv], head-major columns
__global__ __launch_bounds__(128) void qkv_gemm(const float* __restrict__ A,
                                                const float* __restrict__ Wq,
                                                const float* __restrict__ Wk,
                                                const float* __restrict__ Wv,
                                                float* __restrict__ Z) {
    const int M = 100;
    const int m0 = blockIdx.y * 64, n0 = blockIdx.x * 32;
    const float* Bp;
    int ldb;
    if (n0 < 512) { Bp = Wq + (n0 >> 7) * (512 * 128) + (n0 & 127); ldb = 128; }
    else if (n0 < 1024) { int c = n0 - 512; Bp = Wk + (c >> 7) * (512 * 128) + (c & 127); ldb = 128; }
    else { int c = n0 - 1024; Bp = Wv + (c >> 8) * (512 * 256) + (c & 255); ldb = 256; }
    GEMM_CORE(A, 512,
              { *(float4*)(&Bs[bk][bn4]) =
                    *(const float4*)(Bp + (long long)(kk0 + bk) * ldb + bn4); },
              0, 512)
#pragma unroll
    for (int i = 0; i < 4; i++) {
        int m = m0 + (ty << 2) + i;
        if (m >= M) break;
#pragma unroll
        for (int j = 0; j < 4; j++)
            Z[(long long)m * 2048 + n0 + (tx << 2) + j] = acc[i][j];
    }
}

// conv10 as GEMM with transposed B (W[512][1024]) + bias + location embedding -> h
__global__ __launch_bounds__(128) void gemmT_loc(const float* __restrict__ A,
                                                 const float* __restrict__ W,
                                                 const float* __restrict__ bias,
                                                 float* __restrict__ C) {
    const int M = 100;
    const int m0 = blockIdx.y * 64, n0 = blockIdx.x * 32;
    const int bn = threadIdx.x & 31, k4 = ((threadIdx.x >> 5) & 3) << 2;
    GEMM_CORE(A, 1024,
              {
                  float4 wv = *(const float4*)(W + (long long)(n0 + bn) * 1024 + kk0 + k4);
                  Bs[k4 + 0][bn] = wv.x; Bs[k4 + 1][bn] = wv.y;
                  Bs[k4 + 2][bn] = wv.z; Bs[k4 + 3][bn] = wv.w;
              },
              0, 1024)
#pragma unroll
    for (int i = 0; i < 4; i++) {
        int m = m0 + (ty << 2) + i;
        if (m >= M) break;
        float pos = 20.f * (float)(m / 10);
#pragma unroll
        for (int j = 0; j < 4; j++) {
            int n = n0 + (tx << 2) + j;
            float v = acc[i][j] + bias[n];
            int kkn = (n < 256) ? n : n - 256;
            float inv = exp2f(-(2.f * (float)kkn / 256.f) * 13.287712379549449f);
            float ang = pos * inv;
            v += (n < 256) ? sinf(ang) : cosf(ang);
            C[(long long)m * 512 + n] = v;
        }
    }
}

// ---------------- fused attention (reads packed Z) ----------------
__global__ void attn_kernel(const float* __restrict__ Z, float* __restrict__ O) {
    const int n = blockIdx.x, h = blockIdx.y;
    __shared__ float sq[128];
    __shared__ float sa[100];
    __shared__ float red[8];
    const int tid = threadIdx.x;
    if (tid < 128) sq[tid] = Z[n * 2048 + h * 128 + tid];
    __syncthreads();
    float s = -1e30f;
    if (tid < 100) {
        const float* kr = Z + tid * 2048 + 512 + h * 128;
        float acc = 0.f;
#pragma unroll 8
        for (int i = 0; i < 128; i++) acc += sq[i] * kr[i];
        s = acc * 0.1f;
    }
    float v = s;
#pragma unroll
    for (int o = 16; o; o >>= 1) v = fmaxf(v, __shfl_xor_sync(0xffffffffu, v, o));
    if ((tid & 31) == 0) red[tid >> 5] = v;
    __syncthreads();
    float mx = red[0];
#pragma unroll
    for (int i = 1; i < 8; i++) mx = fmaxf(mx, red[i]);
    float e = (tid < 100) ? expf(s - mx) : 0.f;
    float sv = e;
#pragma unroll
    for (int o = 16; o; o >>= 1) sv += __shfl_xor_sync(0xffffffffu, sv, o);
    __syncthreads();
    if ((tid & 31) == 0) red[tid >> 5] = sv;
    __syncthreads();
    float sum = 0.f;
#pragma unroll
    for (int i = 0; i < 8; i++) sum += red[i];
    if (tid < 100) sa[tid] = e / sum;
    __syncthreads();
    const float* vb = Z + 1024 + h * 256;
    float acc = 0.f;
#pragma unroll 4
    for (int m = 0; m < 100; m++) acc += sa[m] * vb[m * 2048 + tid];
    O[n * 1024 + h * 256 + tid] = acc;
}

// ---------------- split-K reduce: h += sum(parts) (+bias) ----------------
template <bool HASB>
__global__ void redAdd(float* __restrict__ h, const float* __restrict__ part,
                       const float* __restrict__ bias) {
    int i = blockIdx.x * blockDim.x + threadIdx.x;
    if (i < 51200) {
        float s = part[i] + part[i + 51200] + part[i + 102400] + part[i + 153600];
        if (HASB) s += bias[i & 511];
        h[i] += s;
    }
}

// ---------------- host launcher ----------------
extern "C" void kernel_launch(void* const* d_in, const int* in_sizes, int n_in,
                              void* d_out, int out_size) {
    const float* x = (const float*)d_in[0];
    const float* cw[10];
    const float* cb[10];
    for (int i = 0; i < 10; i++) {
        cw[i] = (const float*)d_in[1 + 2 * i];
        cb[i] = (const float*)d_in[2 + 2 * i];
    }
    const float* Wq = (const float*)d_in[21];
    const float* Wk = (const float*)d_in[22];
    const float* Wv = (const float*)d_in[23];
    const float* Wo = (const float*)d_in[24];
    const float* W1 = (const float*)d_in[25];
    const float* b1 = (const float*)d_in[26];
    const float* W2 = (const float*)d_in[27];
    const float* b2 = (const float*)d_in[28];
    float* h = (float*)d_out;

    float *bufA, *bufB, *z, *o, *t, *part;
    cudaGetSymbolAddress((void**)&bufA, g_bufA);
    cudaGetSymbolAddress((void**)&bufB, g_bufB);
    cudaGetSymbolAddress((void**)&z, g_z);
    cudaGetSymbolAddress((void**)&o, g_o);
    cudaGetSymbolAddress((void**)&t, g_t);
    cudaGetSymbolAddress((void**)&part, g_part);

    // ---- conv stack ----
    conv1_kernel<<<100, 256>>>(x, cw[0], cb[0], bufA);                       // 3->8, 18
    conv_tile<8, 16, 18, 2, 8, true, 256><<<100, 256>>>(bufA, cw[1], cb[1], bufB);   // 16
    conv_tile<16, 32, 16, 4, 7, false, 224><<<100, 224>>>(bufB, cw[2], cb[2], bufA); // 14
    conv_tile<32, 32, 14, 4, 6, true, 192><<<100, 192>>>(bufA, cw[3], cb[3], bufB);  // 12
    conv_tile<32, 64, 12, 4, 10, true, 160><<<100, 160>>>(bufB, cw[4], cb[4], bufA); // 10
    conv_tile<64, 64, 10, 4, 8, true, 128><<<100, 128>>>(bufA, cw[5], cb[5], bufB);  // 8
    conv_tile<64, 128, 8, 4, 9, true, 128><<<100, 128>>>(bufB, cw[6], cb[6], bufA);  // 6
    conv_tile<128, 128, 6, 4, 4, true, 128><<<100, 128>>>(bufA, cw[7], cb[7], bufB); // 4
    conv_tile<128, 256, 4, 4, 2, true, 128><<<100, 128>>>(bufB, cw[8], cb[8], bufA); // 2
    gemmT_loc<<<dim3(16, 2), 128>>>(bufA, cw[9], cb[9], h);  // 1x1 conv + loc emb

    // ---- 12 encoder layers ----
    for (int l = 0; l < 12; l++) {
        const float* wq = Wq + (size_t)l * 4 * 512 * 128;
        const float* wk = Wk + (size_t)l * 4 * 512 * 128;
        const float* wv = Wv + (size_t)l * 4 * 512 * 256;
        const float* wo = Wo + (size_t)l * 1024 * 512;
        const float* w1 = W1 + (size_t)l * 512 * 2048;
        const float* bb1 = b1 + (size_t)l * 2048;
        const float* w2 = W2 + (size_t)l * 2048 * 512;
        const float* bb2 = b2 + (size_t)l * 512;

        qkv_gemm<<<dim3(64, 2), 128>>>(h, wq, wk, wv, z);
        attn_kernel<<<dim3(100, 4), 256>>>(z, o);
        // h += O @ Wo   (split-K=4 -> partials -> reduce)
        gemmS<false, false, false, true><<<dim3(16, 2, 4), 128>>>(
            o, wo, nullptr, part, 100, 512, 1024, 1024, 512, 512, 256, 51200LL);
        redAdd<false><<<200, 256>>>(h, part, nullptr);
        // t = relu(h @ W1 + b1)
        gemmS<true, true, false, false><<<dim3(64, 2, 1), 128>>>(
            h, w1, bb1, t, 100, 2048, 512, 512, 2048, 2048, 512, 0LL);
        // h += t @ W2 + b2   (split-K=4)
        gemmS<false, false, false, true><<<dim3(16, 2, 4), 128>>>(
            t, w2, nullptr, part, 100, 512, 2048, 2048, 512, 512, 512, 51200LL);
        redAdd<true><<<200, 256>>>(h, part, bb2);
    }
}